// round 1
// baseline (speedup 1.0000x reference)
#include <cuda_runtime.h>
#include <math.h>

// Problem constants
#define N_S 4096
#define N_T 4096
#define R_CONST 0.05f
#define SIGMA 0.2f
#define K_STRIKE 100.0f
#define S_MAX 300.0f
#define B_CONST 100.0f
#define ALPHA_STR 30.0f
#define CHI 6.0f
#define LAMBDA_PDE 1.0f
#define LAMBDA_BC 10.0f
#define LAMBDA_TC 10.0f
#define HUBER_DELTA 0.01f
#define ALPHA 2.5f   /* 2r/sigma^2 = 2*0.05/0.04 */

#define BLOCK_THREADS 256

// Scratch for per-row block partials (no cudaMalloc allowed).
__device__ double g_partials[N_S];

__global__ __launch_bounds__(BLOCK_THREADS)
void bsloss_rows_kernel(const float* __restrict__ V, float c1, float c2,
                        float inv2du, float invdu2, float inv2dt)
{
    const int s   = blockIdx.x;
    const int tid = threadIdx.x;

    // ---- per-row stretch metrics (all threads compute; cheap) ----
    const float du  = 1.0f / (float)(N_S - 1);
    const float u   = (float)s * du;
    const float L   = c2 * u + c1 * (1.0f - u);
    const float dL  = c2 - c1;
    const float S   = B_CONST + ALPHA_STR * (L * L * L / CHI + L);
    const float Su  = ALPHA_STR * dL * (0.5f * L * L + 1.0f);
    const float Suu = ALPHA_STR * dL * dL * L;

    const float Sn   = S   / S_MAX;
    const float Sun  = Su  / S_MAX;
    const float Suun = Suu / S_MAX;

    const float inv_Sun  = 1.0f / Sun;
    const float inv_Sun3 = inv_Sun * inv_Sun * inv_Sun;
    const float Sn2      = Sn * Sn;
    const float aSn      = ALPHA * Sn;

    const float pde_scale = LAMBDA_PDE / (float)((N_S - 2) * (double)(N_T - 2));
    const float bc_scale  = LAMBDA_BC / (float)N_T;
    const float tc_scale  = LAMBDA_TC / (float)N_S;

    const float* row = V + (size_t)s * N_T;

    float acc = 0.0f;

    // ---- PDE residual over interior rows ----
    if (s >= 1 && s <= N_S - 2) {
        const float* rm = row - N_T;
        const float* rp = row + N_T;
        #pragma unroll 4
        for (int t = 1 + tid; t <= N_T - 2; t += BLOCK_THREADS) {
            float vc  = row[t];
            float vm  = rm[t];
            float vp  = rp[t];
            float vu  = (vp - vm) * inv2du;
            float vuu = (vp + vm - 2.0f * vc) * invdu2;
            float vt  = (row[t + 1] - row[t - 1]) * inv2dt;

            float VS  = vu * inv_Sun;
            float VSS = (vuu * Sun - vu * Suun) * inv_Sun3;
            VSS = fminf(100.0f, fmaxf(-100.0f, VSS));

            float res = vt - Sn2 * VSS - aSn * VS + ALPHA * vc;
            acc = fmaf(res * res, pde_scale, acc);
        }
    }

    // ---- far-field BC at s = N_S-1 ----
    if (s == N_S - 1) {
        const float dt_grid = 1.0f / (float)(N_T - 1);
        for (int t = tid; t < N_T; t += BLOCK_THREADS) {
            float tv = (float)t * dt_grid;
            float target = 1.0f - K_STRIKE * __expf(-R_CONST * (1.0f - tv)) / S_MAX;
            float d = row[t] - target;
            acc = fmaf(d * d, bc_scale, acc);
        }
    }

    // ---- terminal (Huber) at t = N_T-1: one element per row ----
    if (tid == 0) {
        float x = 50.0f * (u - K_STRIKE / S_MAX);
        float payoff = (fmaxf(x, 0.0f) + log1pf(expf(-fabsf(x)))) / 50.0f;
        float d  = row[N_T - 1] - payoff;
        float ad = fabsf(d);
        float h  = (ad < HUBER_DELTA) ? (0.5f * d * d)
                                      : (HUBER_DELTA * (ad - 0.5f * HUBER_DELTA));
        acc += h * tc_scale;
    }

    // ---- block reduction (fp32 tree; partials are O(10-100) each) ----
    __shared__ float smem[BLOCK_THREADS];
    smem[tid] = acc;
    __syncthreads();
    #pragma unroll
    for (int off = BLOCK_THREADS / 2; off >= 32; off >>= 1) {
        if (tid < off) smem[tid] += smem[tid + off];
        __syncthreads();
    }
    if (tid < 32) {
        float v = smem[tid];
        #pragma unroll
        for (int off = 16; off > 0; off >>= 1)
            v += __shfl_down_sync(0xFFFFFFFFu, v, off);
        if (tid == 0) g_partials[s] = (double)v;
    }
}

__global__ __launch_bounds__(1024)
void bsloss_finalize_kernel(float* __restrict__ out)
{
    const int tid = threadIdx.x;
    double a = 0.0;
    for (int i = tid; i < N_S; i += 1024) a += g_partials[i];

    __shared__ double smem[1024];
    smem[tid] = a;
    __syncthreads();
    #pragma unroll
    for (int off = 512; off >= 32; off >>= 1) {
        if (tid < off) smem[tid] += smem[tid + off];
        __syncthreads();
    }
    if (tid < 32) {
        double v = smem[tid];
        #pragma unroll
        for (int off = 16; off > 0; off >>= 1)
            v += __shfl_down_sync(0xFFFFFFFFu, v, off);
        if (tid == 0) out[0] = (float)v;
    }
}

// Host-side: cubic stretching roots (deterministic double math, cheap per call).
static double solve_depressed_cubic(double Q) {
    double p = 6.0;               // CHI
    double q = 6.0 * Q;
    double sp = sqrt(p);
    double arg = fabs(q) / (2.0 * p * sp / (3.0 * sqrt(3.0)));
    if (arg < 1.0) arg = 1.0;
    double c = 2.0 * sp * cosh(acosh(arg) / 3.0);
    return (q >= 0.0) ? -c : c;
}

extern "C" void kernel_launch(void* const* d_in, const int* in_sizes, int n_in,
                              void* d_out, int out_size)
{
    (void)in_sizes; (void)n_in; (void)out_size;
    const float* V = (const float*)d_in[0];
    float* out = (float*)d_out;

    const double c1d = solve_depressed_cubic((100.0 - 0.0) / 30.0);
    const double c2d = solve_depressed_cubic((100.0 - 300.0) / 30.0);

    // FD scale factors (computed in double, passed as float — matches f32 math
    // within last-ulp of the reference's scalar-divide).
    const double DU = 1.0 / (double)(N_S - 1);
    const double TAU_MAX = 0.5 * 0.2 * 0.2 * 1.0;
    const double DT_NORM = TAU_MAX / (double)(N_T - 1);

    const float inv2du = (float)(1.0 / (2.0 * DU));
    const float invdu2 = (float)(1.0 / (DU * DU));
    const float inv2dt = (float)(1.0 / (2.0 * DT_NORM));

    bsloss_rows_kernel<<<N_S, BLOCK_THREADS>>>(V, (float)c1d, (float)c2d,
                                               inv2du, invdu2, inv2dt);
    bsloss_finalize_kernel<<<1, 1024>>>(out);
}

// round 2
// speedup vs baseline: 1.0315x; 1.0315x over previous
#include <cuda_runtime.h>
#include <math.h>

#define N_S 4096
#define N_T 4096
#define R_CONST 0.05f
#define K_STRIKE 100.0f
#define S_MAX 300.0f
#define B_CONST 100.0f
#define ALPHA_STR 30.0f
#define CHI 6.0f
#define LAMBDA_BC 10.0f
#define LAMBDA_TC 10.0f
#define HUBER_DELTA 0.01f
#define ALPHA 2.5f

#define BLOCK_THREADS 256
// vector chunks cover t in [4, 4092): 1022 float4 chunks; scalars t=1,2,3,4092,4093,4094
#define NCHUNK 1022

__device__ float    g_partials[N_S];
__device__ unsigned g_count = 0;

__global__ __launch_bounds__(BLOCK_THREADS)
void bsloss_fused_kernel(const float* __restrict__ V, float* __restrict__ out,
                         float c1, float c2,
                         float inv2du, float invdu2, float inv2dt,
                         float pde_scale, float bc_scale, float tc_scale)
{
    const int s   = blockIdx.x;
    const int tid = threadIdx.x;

    // per-row stretch metrics
    const float du   = 1.0f / (float)(N_S - 1);
    const float u    = (float)s * du;
    const float L    = c2 * u + c1 * (1.0f - u);
    const float dL   = c2 - c1;
    const float S    = B_CONST + ALPHA_STR * (L * L * L / CHI + L);
    const float Sun  = (ALPHA_STR * dL * (0.5f * L * L + 1.0f)) / S_MAX;
    const float Suun = (ALPHA_STR * dL * dL * L) / S_MAX;
    const float Sn   = S / S_MAX;

    const float inv_Sun  = 1.0f / Sun;
    const float inv_Sun3 = inv_Sun * inv_Sun * inv_Sun;
    const float Sn2      = Sn * Sn;
    const float aSn      = ALPHA * Sn;

    const float* row = V + (size_t)s * N_T;

    float acc = 0.0f;

    auto elem = [&](float vc, float vm, float vp, float tl, float tr) {
        float vu  = (vp - vm) * inv2du;
        float vuu = (vp + vm - 2.0f * vc) * invdu2;
        float vt  = (tr - tl) * inv2dt;
        float VS  = vu * inv_Sun;
        float VSS = (vuu * Sun - vu * Suun) * inv_Sun3;
        VSS = fminf(100.0f, fmaxf(-100.0f, VSS));
        float res = vt - Sn2 * VSS - aSn * VS + ALPHA * vc;
        acc = fmaf(res * res, pde_scale, acc);
    };

    if (s >= 1 && s <= N_S - 2) {
        const float* rm = row - N_T;
        const float* rp = row + N_T;

        for (int idx = tid; idx < NCHUNK; idx += BLOCK_THREADS) {
            const int t0 = 4 + idx * 4;
            float4 c4 = *(const float4*)(row + t0);
            float4 m4 = *(const float4*)(rm  + t0);
            float4 p4 = *(const float4*)(rp  + t0);
            float left  = row[t0 - 1];
            float right = row[t0 + 4];
            elem(c4.x, m4.x, p4.x, left, c4.y);
            elem(c4.y, m4.y, p4.y, c4.x, c4.z);
            elem(c4.z, m4.z, p4.z, c4.y, c4.w);
            elem(c4.w, m4.w, p4.w, c4.z, right);
        }
        if (tid < 6) {
            int t = (tid < 3) ? (1 + tid) : (4092 + tid - 3);
            elem(row[t], rm[t], rp[t], row[t - 1], row[t + 1]);
        }
    }

    if (s == N_S - 1) {
        const float dt_grid = 1.0f / (float)(N_T - 1);
        for (int t = tid; t < N_T; t += BLOCK_THREADS) {
            float tv = (float)t * dt_grid;
            float target = 1.0f - K_STRIKE * __expf(-R_CONST * (1.0f - tv)) / S_MAX;
            float d = row[t] - target;
            acc = fmaf(d * d, bc_scale, acc);
        }
    }

    if (tid == 0) {
        float x = 50.0f * (u - K_STRIKE / S_MAX);
        float payoff = (fmaxf(x, 0.0f) + log1pf(expf(-fabsf(x)))) / 50.0f;
        float d  = row[N_T - 1] - payoff;
        float ad = fabsf(d);
        float h  = (ad < HUBER_DELTA) ? (0.5f * d * d)
                                      : (HUBER_DELTA * (ad - 0.5f * HUBER_DELTA));
        acc += h * tc_scale;
    }

    // ---- block reduction ----
    __shared__ float smem[BLOCK_THREADS];
    smem[tid] = acc;
    __syncthreads();
    #pragma unroll
    for (int off = BLOCK_THREADS / 2; off >= 32; off >>= 1) {
        if (tid < off) smem[tid] += smem[tid + off];
        __syncthreads();
    }
    if (tid < 32) {
        float v = smem[tid];
        #pragma unroll
        for (int off = 16; off > 0; off >>= 1)
            v += __shfl_down_sync(0xFFFFFFFFu, v, off);
        if (tid == 0) g_partials[s] = v;
    }

    // ---- last-block deterministic finalize (no separate launch) ----
    __shared__ bool is_last;
    __threadfence();
    if (tid == 0) {
        unsigned prev = atomicAdd(&g_count, 1u);
        is_last = (prev == (unsigned)(gridDim.x - 1));
    }
    __syncthreads();
    if (is_last) {
        // fixed-order tree over fixed indices: bit-deterministic
        double a = 0.0;
        #pragma unroll
        for (int k = 0; k < N_S / BLOCK_THREADS; k++)
            a += (double)__ldcg(&g_partials[tid + k * BLOCK_THREADS]);

        __shared__ double dsm[BLOCK_THREADS];
        dsm[tid] = a;
        __syncthreads();
        #pragma unroll
        for (int off = BLOCK_THREADS / 2; off >= 1; off >>= 1) {
            if (tid < off) dsm[tid] += dsm[tid + off];
            __syncthreads();
        }
        if (tid == 0) {
            out[0] = (float)dsm[0];
            g_count = 0;   // reset for next graph replay
        }
    }
}

static double solve_depressed_cubic(double Q) {
    double p = 6.0;
    double q = 6.0 * Q;
    double sp = sqrt(p);
    double arg = fabs(q) / (2.0 * p * sp / (3.0 * sqrt(3.0)));
    if (arg < 1.0) arg = 1.0;
    double c = 2.0 * sp * cosh(acosh(arg) / 3.0);
    return (q >= 0.0) ? -c : c;
}

extern "C" void kernel_launch(void* const* d_in, const int* in_sizes, int n_in,
                              void* d_out, int out_size)
{
    (void)in_sizes; (void)n_in; (void)out_size;
    const float* V = (const float*)d_in[0];
    float* out = (float*)d_out;

    const double c1d = solve_depressed_cubic((100.0 - 0.0) / 30.0);
    const double c2d = solve_depressed_cubic((100.0 - 300.0) / 30.0);

    const double DU = 1.0 / (double)(N_S - 1);
    const double TAU_MAX = 0.5 * 0.2 * 0.2 * 1.0;
    const double DT_NORM = TAU_MAX / (double)(N_T - 1);

    const float inv2du = (float)(1.0 / (2.0 * DU));
    const float invdu2 = (float)(1.0 / (DU * DU));
    const float inv2dt = (float)(1.0 / (2.0 * DT_NORM));

    const float pde_scale = (float)(1.0 / ((double)(N_S - 2) * (double)(N_T - 2)));
    const float bc_scale  = (float)(10.0 / (double)N_T);
    const float tc_scale  = (float)(10.0 / (double)N_S);

    bsloss_fused_kernel<<<N_S, BLOCK_THREADS>>>(V, out, (float)c1d, (float)c2d,
                                                inv2du, invdu2, inv2dt,
                                                pde_scale, bc_scale, tc_scale);
}

// round 3
// speedup vs baseline: 1.1972x; 1.1606x over previous
#include <cuda_runtime.h>
#include <math.h>

#define N_S 4096
#define N_T 4096
#define R_CONST 0.05f
#define K_STRIKE 100.0f
#define S_MAX 300.0f
#define B_CONST 100.0f
#define ALPHA_STR 30.0f
#define CHI 6.0f
#define HUBER_DELTA 0.01f
#define ALPHA 2.5f

#define BLOCK_THREADS 256
#define ROWS_PER_TILE 4
#define NP_BLOCKS 4097   /* 1 tail block + 4096 PDE tiles */

typedef unsigned long long u64;

__device__ float    g_partials[NP_BLOCKS];
__device__ unsigned g_count = 0;

__device__ __forceinline__ u64 pk(float lo, float hi) {
    u64 r; asm("mov.b64 %0,{%1,%2};" : "=l"(r) : "f"(lo), "f"(hi)); return r;
}
__device__ __forceinline__ void upk(u64 v, float& lo, float& hi) {
    asm("mov.b64 {%0,%1},%2;" : "=f"(lo), "=f"(hi) : "l"(v));
}
__device__ __forceinline__ u64 f2fma(u64 a, u64 b, u64 c) {
    u64 r; asm("fma.rn.f32x2 %0,%1,%2,%3;" : "=l"(r) : "l"(a), "l"(b), "l"(c)); return r;
}
__device__ __forceinline__ u64 f2mul(u64 a, u64 b) {
    u64 r; asm("mul.rn.f32x2 %0,%1,%2;" : "=l"(r) : "l"(a), "l"(b)); return r;
}
__device__ __forceinline__ u64 f2add(u64 a, u64 b) {
    u64 r; asm("add.rn.f32x2 %0,%1,%2;" : "=l"(r) : "l"(a), "l"(b)); return r;
}

__global__ __launch_bounds__(BLOCK_THREADS)
void bsloss_fused_kernel(const float* __restrict__ V, float* __restrict__ out,
                         float c1, float c2,
                         float inv2du, float invdu2, float inv2dt,
                         float pde_scale, float bc_scale, float tc_scale)
{
    const int bid = blockIdx.x;
    const int tid = threadIdx.x;
    const float du = 1.0f / (float)(N_S - 1);

    float partial = 0.0f;

    __shared__ float sm_k[ROWS_PER_TILE][5];

    if (bid == 0) {
        // ---------- tail block: BC row (s=4095) + terminal column (t=4095) ----------
        float acc = 0.0f;
        const float* brow = V + (size_t)(N_S - 1) * N_T;
        const float dt_grid = 1.0f / (float)(N_T - 1);
        #pragma unroll
        for (int k = 0; k < 4; k++) {
            int t0 = (tid + 256 * k) * 4;
            float4 v4 = *(const float4*)(brow + t0);
            #pragma unroll
            for (int j = 0; j < 4; j++) {
                float v = (j == 0) ? v4.x : (j == 1) ? v4.y : (j == 2) ? v4.z : v4.w;
                float tv = (float)(t0 + j) * dt_grid;
                float target = 1.0f - K_STRIKE * __expf(-R_CONST * (1.0f - tv)) / S_MAX;
                float d = v - target;
                acc = fmaf(d * d, bc_scale, acc);
            }
        }
        #pragma unroll
        for (int k = 0; k < 16; k++) {
            int s = tid + 256 * k;
            float v = __ldg(V + (size_t)s * N_T + (N_T - 1));
            float u = (float)s * du;
            float x = 50.0f * (u - K_STRIKE / S_MAX);
            float payoff = (fmaxf(x, 0.0f) + log1pf(expf(-fabsf(x)))) / 50.0f;
            float d  = v - payoff;
            float ad = fabsf(d);
            float h  = (ad < HUBER_DELTA) ? (0.5f * d * d)
                                          : (HUBER_DELTA * (ad - 0.5f * HUBER_DELTA));
            acc = fmaf(h, tc_scale, acc);
        }
        partial = acc;
    } else {
        // ---------- PDE tile: 4 rows x 1024 t-elems ----------
        const int tile = bid - 1;
        const int btx  = tile & 3;        // t-quadrant
        const int bty  = tile >> 2;       // row tile
        const int s0   = 1 + ROWS_PER_TILE * bty;

        if (tid < ROWS_PER_TILE) {
            int s = s0 + tid;
            float u   = (float)s * du;
            float L   = c2 * u + c1 * (1.0f - u);
            float dL  = c2 - c1;
            float Sun  = (ALPHA_STR * dL * (0.5f * L * L + 1.0f)) / S_MAX;
            float Suun = (ALPHA_STR * dL * dL * L) / S_MAX;
            float Sn   = (B_CONST + ALPHA_STR * (L * L * L / CHI + L)) / S_MAX;
            float iS  = 1.0f / Sun;
            float iS2 = iS * iS;
            float iS3 = iS2 * iS;
            sm_k[tid][0] = invdu2 * iS2;                    // kA
            sm_k[tid][1] = -(inv2du * Suun * iS3);          // kBn
            sm_k[tid][2] = -(ALPHA * Sn * iS * inv2du);     // kCn
            sm_k[tid][3] = -(Sn * Sn);                      // Sn2n
            sm_k[tid][4] = (s <= N_S - 2) ? pde_scale : 0.0f;
        }
        __syncthreads();

        const int chunk = btx * 256 + tid;   // 0..1023
        const int t0    = chunk * 4;

        // 6 row loads (rows s0-1 .. s0+4, clamped)
        ulonglong2 q[6];
        #pragma unroll
        for (int r = 0; r < 6; r++) {
            int srow = s0 - 1 + r;
            srow = (srow > N_S - 1) ? (N_S - 1) : srow;
            q[r] = *(const ulonglong2*)(V + (size_t)srow * N_T + t0);
        }
        // t-neighbor scalars for center rows (clamped so clamp-row reads stay in-bounds)
        float lf[ROWS_PER_TILE], rt[ROWS_PER_TILE];
        #pragma unroll
        for (int r = 0; r < ROWS_PER_TILE; r++) {
            int srow = s0 + r;
            srow = (srow > N_S - 2) ? (N_S - 2) : srow;
            const float* row = V + (size_t)srow * N_T;
            lf[r] = row[t0 - 1];      // chunk==0 -> prev row's last elem (masked)
            rt[r] = row[t0 + 4];      // chunk==1023 -> next row's first elem (masked)
        }

        const u64 M1  = pk(-1.0f, -1.0f);
        const u64 M2  = pk(-2.0f, -2.0f);
        const u64 DT2 = pk(inv2dt, inv2dt);
        const u64 AL2 = pk(ALPHA, ALPHA);
        const u64 mask1 = (chunk == 0)    ? 0xFFFFFFFF00000000ull : ~0ull;
        const u64 mask2 = (chunk == 1023) ? 0x00000000FFFFFFFFull : ~0ull;

        u64 acc2 = 0;  // packed (+0, +0)

        #pragma unroll
        for (int r = 0; r < ROWS_PER_TILE; r++) {
            const float kA   = sm_k[r][0];
            const float kBn  = sm_k[r][1];
            const float kCn  = sm_k[r][2];
            const float Sn2n = sm_k[r][3];
            const float ps   = sm_k[r][4];
            const u64 kA2   = pk(kA, kA);
            const u64 kBn2  = pk(kBn, kBn);
            const u64 kCn2  = pk(kCn, kCn);
            const u64 Sn2n2 = pk(Sn2n, Sn2n);
            const u64 PS2   = pk(ps, ps);

            const u64 vm01 = q[r].x,     vm23 = q[r].y;
            const u64 vc01 = q[r + 1].x, vc23 = q[r + 1].y;
            const u64 vp01 = q[r + 2].x, vp23 = q[r + 2].y;

            float cx, cy, cz, cw;
            upk(vc01, cx, cy);
            upk(vc23, cz, cw);
            const u64 tl1 = pk(lf[r], cx);
            const u64 mid = pk(cy, cz);
            const u64 tr2 = pk(cw, rt[r]);
            const u64 vtd1 = f2fma(tl1, M1, mid);   // tr - tl for elems (t0, t0+1)
            const u64 vtd2 = f2fma(mid, M1, tr2);   // for elems (t0+2, t0+3)

            // ---- pair 1 ----
            {
                u64 d   = f2fma(vm01, M1, vp01);
                u64 e   = f2fma(vc01, M2, f2add(vp01, vm01));
                u64 VSS = f2fma(d, kBn2, f2mul(e, kA2));
                float a, b;
                upk(VSS, a, b);
                a = fminf(100.0f, fmaxf(-100.0f, a));
                b = fminf(100.0f, fmaxf(-100.0f, b));
                u64 VSSc = pk(a, b);
                u64 res = f2fma(vc01, AL2,
                           f2fma(d, kCn2,
                            f2fma(VSSc, Sn2n2, f2mul(vtd1, DT2))));
                u64 sq = f2mul(res, res) & mask1;
                acc2 = f2fma(sq, PS2, acc2);
            }
            // ---- pair 2 ----
            {
                u64 d   = f2fma(vm23, M1, vp23);
                u64 e   = f2fma(vc23, M2, f2add(vp23, vm23));
                u64 VSS = f2fma(d, kBn2, f2mul(e, kA2));
                float a, b;
                upk(VSS, a, b);
                a = fminf(100.0f, fmaxf(-100.0f, a));
                b = fminf(100.0f, fmaxf(-100.0f, b));
                u64 VSSc = pk(a, b);
                u64 res = f2fma(vc23, AL2,
                           f2fma(d, kCn2,
                            f2fma(VSSc, Sn2n2, f2mul(vtd2, DT2))));
                u64 sq = f2mul(res, res) & mask2;
                acc2 = f2fma(sq, PS2, acc2);
            }
        }
        float alo, ahi;
        upk(acc2, alo, ahi);
        partial = alo + ahi;
    }

    // ---------- block reduction ----------
    __shared__ float smem[BLOCK_THREADS];
    smem[tid] = partial;
    __syncthreads();
    #pragma unroll
    for (int off = BLOCK_THREADS / 2; off >= 32; off >>= 1) {
        if (tid < off) smem[tid] += smem[tid + off];
        __syncthreads();
    }
    if (tid < 32) {
        float v = smem[tid];
        #pragma unroll
        for (int off = 16; off > 0; off >>= 1)
            v += __shfl_down_sync(0xFFFFFFFFu, v, off);
        if (tid == 0) g_partials[bid] = v;
    }

    // ---------- last-block deterministic finalize ----------
    __shared__ bool is_last;
    __threadfence();
    if (tid == 0) {
        unsigned prev = atomicAdd(&g_count, 1u);
        is_last = (prev == (unsigned)(gridDim.x - 1));
    }
    __syncthreads();
    if (is_last) {
        double a = 0.0;
        #pragma unroll
        for (int k = 0; k < 17; k++) {
            int idx = tid + k * BLOCK_THREADS;
            if (idx < NP_BLOCKS) a += (double)__ldcg(&g_partials[idx]);
        }
        __shared__ double dsm[BLOCK_THREADS];
        dsm[tid] = a;
        __syncthreads();
        #pragma unroll
        for (int off = BLOCK_THREADS / 2; off >= 1; off >>= 1) {
            if (tid < off) dsm[tid] += dsm[tid + off];
            __syncthreads();
        }
        if (tid == 0) {
            out[0] = (float)dsm[0];
            g_count = 0;   // reset for next graph replay
        }
    }
}

static double solve_depressed_cubic(double Q) {
    double p = 6.0;
    double q = 6.0 * Q;
    double sp = sqrt(p);
    double arg = fabs(q) / (2.0 * p * sp / (3.0 * sqrt(3.0)));
    if (arg < 1.0) arg = 1.0;
    double c = 2.0 * sp * cosh(acosh(arg) / 3.0);
    return (q >= 0.0) ? -c : c;
}

extern "C" void kernel_launch(void* const* d_in, const int* in_sizes, int n_in,
                              void* d_out, int out_size)
{
    (void)in_sizes; (void)n_in; (void)out_size;
    const float* V = (const float*)d_in[0];
    float* out = (float*)d_out;

    const double c1d = solve_depressed_cubic((100.0 - 0.0) / 30.0);
    const double c2d = solve_depressed_cubic((100.0 - 300.0) / 30.0);

    const double DU = 1.0 / (double)(N_S - 1);
    const double TAU_MAX = 0.5 * 0.2 * 0.2 * 1.0;
    const double DT_NORM = TAU_MAX / (double)(N_T - 1);

    const float inv2du = (float)(1.0 / (2.0 * DU));
    const float invdu2 = (float)(1.0 / (DU * DU));
    const float inv2dt = (float)(1.0 / (2.0 * DT_NORM));

    const float pde_scale = (float)(1.0 / ((double)(N_S - 2) * (double)(N_T - 2)));
    const float bc_scale  = (float)(10.0 / (double)N_T);
    const float tc_scale  = (float)(10.0 / (double)N_S);

    bsloss_fused_kernel<<<NP_BLOCKS, BLOCK_THREADS>>>(V, out, (float)c1d, (float)c2d,
                                                      inv2du, invdu2, inv2dt,
                                                      pde_scale, bc_scale, tc_scale);
}

// round 4
// speedup vs baseline: 1.4083x; 1.1764x over previous
#include <cuda_runtime.h>
#include <math.h>

#define N_S 4096
#define N_T 4096
#define R_CONST 0.05f
#define K_STRIKE 100.0f
#define S_MAX 300.0f
#define B_CONST 100.0f
#define ALPHA_STR 30.0f
#define CHI 6.0f
#define HUBER_DELTA 0.01f
#define ALPHA 2.5f

#define BLOCK_THREADS 256
#define ROWS_PER_TILE 8
#define NP_BLOCKS (512 * 4 + 1)   /* 1 tail block + 2048 PDE tiles */

typedef unsigned long long u64;

__device__ float    g_partials[NP_BLOCKS];
__device__ unsigned g_count = 0;

__device__ __forceinline__ u64 pk(float lo, float hi) {
    u64 r; asm("mov.b64 %0,{%1,%2};" : "=l"(r) : "f"(lo), "f"(hi)); return r;
}
__device__ __forceinline__ void upk(u64 v, float& lo, float& hi) {
    asm("mov.b64 {%0,%1},%2;" : "=f"(lo), "=f"(hi) : "l"(v));
}
__device__ __forceinline__ u64 f2fma(u64 a, u64 b, u64 c) {
    u64 r; asm("fma.rn.f32x2 %0,%1,%2,%3;" : "=l"(r) : "l"(a), "l"(b), "l"(c)); return r;
}
__device__ __forceinline__ u64 f2mul(u64 a, u64 b) {
    u64 r; asm("mul.rn.f32x2 %0,%1,%2;" : "=l"(r) : "l"(a), "l"(b)); return r;
}
__device__ __forceinline__ u64 f2add(u64 a, u64 b) {
    u64 r; asm("add.rn.f32x2 %0,%1,%2;" : "=l"(r) : "l"(a), "l"(b)); return r;
}

__global__ __launch_bounds__(BLOCK_THREADS)
void bsloss_fused_kernel(const float* __restrict__ V, float* __restrict__ out,
                         float c1, float c2,
                         float inv2du, float invdu2, float inv2dt,
                         float pde_scale, float bc_scale, float tc_scale)
{
    const int bid = blockIdx.x;
    const int tid = threadIdx.x;
    const float du = 1.0f / (float)(N_S - 1);

    float partial = 0.0f;

    __shared__ float sm_k[ROWS_PER_TILE][5];

    if (bid == 0) {
        // ---------- tail block: BC row (s=4095) + terminal column (t=4095) ----------
        float acc = 0.0f;
        const float* brow = V + (size_t)(N_S - 1) * N_T;
        const float dt_grid = 1.0f / (float)(N_T - 1);
        #pragma unroll
        for (int k = 0; k < 4; k++) {
            int t0 = (tid + 256 * k) * 4;
            float4 v4 = *(const float4*)(brow + t0);
            #pragma unroll
            for (int j = 0; j < 4; j++) {
                float v = (j == 0) ? v4.x : (j == 1) ? v4.y : (j == 2) ? v4.z : v4.w;
                float tv = (float)(t0 + j) * dt_grid;
                float target = 1.0f - K_STRIKE * __expf(-R_CONST * (1.0f - tv)) / S_MAX;
                float d = v - target;
                acc = fmaf(d * d, bc_scale, acc);
            }
        }
        #pragma unroll
        for (int k = 0; k < 16; k++) {
            int s = tid + 256 * k;
            float v = __ldg(V + (size_t)s * N_T + (N_T - 1));
            float u = (float)s * du;
            float x = 50.0f * (u - K_STRIKE / S_MAX);
            float payoff = (fmaxf(x, 0.0f) + log1pf(expf(-fabsf(x)))) / 50.0f;
            float d  = v - payoff;
            float ad = fabsf(d);
            float h  = (ad < HUBER_DELTA) ? (0.5f * d * d)
                                          : (HUBER_DELTA * (ad - 0.5f * HUBER_DELTA));
            acc = fmaf(h, tc_scale, acc);
        }
        partial = acc;
    } else {
        // ---------- PDE tile: 8 rows x 1024 t-elems ----------
        const int tile = bid - 1;
        const int btx  = tile & 3;        // t-quadrant
        const int bty  = tile >> 2;       // row tile
        const int s0   = 1 + ROWS_PER_TILE * bty;

        if (tid < ROWS_PER_TILE) {
            int s = s0 + tid;
            float u   = (float)s * du;
            float L   = c2 * u + c1 * (1.0f - u);
            float dL  = c2 - c1;
            float Sun  = (ALPHA_STR * dL * (0.5f * L * L + 1.0f)) / S_MAX;
            float Suun = (ALPHA_STR * dL * dL * L) / S_MAX;
            float Sn   = (B_CONST + ALPHA_STR * (L * L * L / CHI + L)) / S_MAX;
            float iS  = 1.0f / Sun;
            float iS2 = iS * iS;
            float iS3 = iS2 * iS;
            sm_k[tid][0] = invdu2 * iS2;                    // kA
            sm_k[tid][1] = -(inv2du * Suun * iS3);          // kBn
            sm_k[tid][2] = -(ALPHA * Sn * iS * inv2du);     // kCn
            sm_k[tid][3] = -(Sn * Sn);                      // Sn2n
            sm_k[tid][4] = (s <= N_S - 2) ? pde_scale : 0.0f;
        }
        __syncthreads();

        const int chunk = btx * 256 + tid;   // 0..1023
        const int t0    = chunk * 4;
        const int lane  = tid & 31;

        // 10 row vector loads (rows s0-1 .. s0+8, clamped), all issued upfront (MLP=10)
        ulonglong2 q[ROWS_PER_TILE + 2];
        #pragma unroll
        for (int r = 0; r < ROWS_PER_TILE + 2; r++) {
            int srow = s0 - 1 + r;
            srow = (srow > N_S - 1) ? (N_S - 1) : srow;
            q[r] = *(const ulonglong2*)(V + (size_t)srow * N_T + t0);
        }

        // boundary-lane t-neighbors (1 line each, issued upfront; interior lanes use shuffles)
        float edgeL[ROWS_PER_TILE], edgeR[ROWS_PER_TILE];
        #pragma unroll
        for (int r = 0; r < ROWS_PER_TILE; r++) { edgeL[r] = 0.0f; edgeR[r] = 0.0f; }
        if (lane == 0 && chunk != 0) {
            #pragma unroll
            for (int r = 0; r < ROWS_PER_TILE; r++) {
                int srow = s0 + r; srow = (srow > N_S - 1) ? (N_S - 1) : srow;
                edgeL[r] = __ldg(V + (size_t)srow * N_T + t0 - 1);
            }
        }
        if (lane == 31 && chunk != 1023) {
            #pragma unroll
            for (int r = 0; r < ROWS_PER_TILE; r++) {
                int srow = s0 + r; srow = (srow > N_S - 1) ? (N_S - 1) : srow;
                edgeR[r] = __ldg(V + (size_t)srow * N_T + t0 + 4);
            }
        }

        const u64 M1  = pk(-1.0f, -1.0f);
        const u64 M2  = pk(-2.0f, -2.0f);
        const u64 DT2 = pk(inv2dt, inv2dt);
        const u64 AL2 = pk(ALPHA, ALPHA);
        const u64 mask1 = (chunk == 0)    ? 0xFFFFFFFF00000000ull : ~0ull;
        const u64 mask2 = (chunk == 1023) ? 0x00000000FFFFFFFFull : ~0ull;

        u64 acc2 = 0;  // packed (+0, +0)

        #pragma unroll
        for (int r = 0; r < ROWS_PER_TILE; r++) {
            const float kA   = sm_k[r][0];
            const float kBn  = sm_k[r][1];
            const float kCn  = sm_k[r][2];
            const float Sn2n = sm_k[r][3];
            const float ps   = sm_k[r][4];
            const u64 kA2   = pk(kA, kA);
            const u64 kBn2  = pk(kBn, kBn);
            const u64 kCn2  = pk(kCn, kCn);
            const u64 Sn2n2 = pk(Sn2n, Sn2n);
            const u64 PS2   = pk(ps, ps);

            const u64 vm01 = q[r].x,     vm23 = q[r].y;
            const u64 vc01 = q[r + 1].x, vc23 = q[r + 1].y;
            const u64 vp01 = q[r + 2].x, vp23 = q[r + 2].y;

            float cx, cy, cz, cw;
            upk(vc01, cx, cy);
            upk(vc23, cz, cw);

            // t-neighbors across chunk boundaries via warp shuffle
            float lfv = __shfl_up_sync(0xFFFFFFFFu, cw, 1);
            float rtv = __shfl_down_sync(0xFFFFFFFFu, cx, 1);
            if (lane == 0)  lfv = edgeL[r];
            if (lane == 31) rtv = edgeR[r];

            const u64 tl1 = pk(lfv, cx);
            const u64 mid = pk(cy, cz);
            const u64 tr2 = pk(cw, rtv);
            const u64 vtd1 = f2fma(tl1, M1, mid);   // tr - tl for elems (t0, t0+1)
            const u64 vtd2 = f2fma(mid, M1, tr2);   // for elems (t0+2, t0+3)

            // ---- pair 1 ----
            {
                u64 d   = f2fma(vm01, M1, vp01);
                u64 e   = f2fma(vc01, M2, f2add(vp01, vm01));
                u64 VSS = f2fma(d, kBn2, f2mul(e, kA2));
                float a, b;
                upk(VSS, a, b);
                a = fminf(100.0f, fmaxf(-100.0f, a));
                b = fminf(100.0f, fmaxf(-100.0f, b));
                u64 VSSc = pk(a, b);
                u64 res = f2fma(vc01, AL2,
                           f2fma(d, kCn2,
                            f2fma(VSSc, Sn2n2, f2mul(vtd1, DT2))));
                u64 sq = f2mul(res, res) & mask1;
                acc2 = f2fma(sq, PS2, acc2);
            }
            // ---- pair 2 ----
            {
                u64 d   = f2fma(vm23, M1, vp23);
                u64 e   = f2fma(vc23, M2, f2add(vp23, vm23));
                u64 VSS = f2fma(d, kBn2, f2mul(e, kA2));
                float a, b;
                upk(VSS, a, b);
                a = fminf(100.0f, fmaxf(-100.0f, a));
                b = fminf(100.0f, fmaxf(-100.0f, b));
                u64 VSSc = pk(a, b);
                u64 res = f2fma(vc23, AL2,
                           f2fma(d, kCn2,
                            f2fma(VSSc, Sn2n2, f2mul(vtd2, DT2))));
                u64 sq = f2mul(res, res) & mask2;
                acc2 = f2fma(sq, PS2, acc2);
            }
        }
        float alo, ahi;
        upk(acc2, alo, ahi);
        partial = alo + ahi;
    }

    // ---------- block reduction ----------
    __shared__ float smem[BLOCK_THREADS];
    smem[tid] = partial;
    __syncthreads();
    #pragma unroll
    for (int off = BLOCK_THREADS / 2; off >= 32; off >>= 1) {
        if (tid < off) smem[tid] += smem[tid + off];
        __syncthreads();
    }
    if (tid < 32) {
        float v = smem[tid];
        #pragma unroll
        for (int off = 16; off > 0; off >>= 1)
            v += __shfl_down_sync(0xFFFFFFFFu, v, off);
        if (tid == 0) g_partials[bid] = v;
    }

    // ---------- last-block deterministic finalize ----------
    __shared__ bool is_last;
    __threadfence();
    if (tid == 0) {
        unsigned prev = atomicAdd(&g_count, 1u);
        is_last = (prev == (unsigned)(gridDim.x - 1));
    }
    __syncthreads();
    if (is_last) {
        double a = 0.0;
        #pragma unroll
        for (int k = 0; k < 9; k++) {
            int idx = tid + k * BLOCK_THREADS;
            if (idx < NP_BLOCKS) a += (double)__ldcg(&g_partials[idx]);
        }
        __shared__ double dsm[BLOCK_THREADS];
        dsm[tid] = a;
        __syncthreads();
        #pragma unroll
        for (int off = BLOCK_THREADS / 2; off >= 1; off >>= 1) {
            if (tid < off) dsm[tid] += dsm[tid + off];
            __syncthreads();
        }
        if (tid == 0) {
            out[0] = (float)dsm[0];
            g_count = 0;   // reset for next graph replay
        }
    }
}

static double solve_depressed_cubic(double Q) {
    double p = 6.0;
    double q = 6.0 * Q;
    double sp = sqrt(p);
    double arg = fabs(q) / (2.0 * p * sp / (3.0 * sqrt(3.0)));
    if (arg < 1.0) arg = 1.0;
    double c = 2.0 * sp * cosh(acosh(arg) / 3.0);
    return (q >= 0.0) ? -c : c;
}

extern "C" void kernel_launch(void* const* d_in, const int* in_sizes, int n_in,
                              void* d_out, int out_size)
{
    (void)in_sizes; (void)n_in; (void)out_size;
    const float* V = (const float*)d_in[0];
    float* out = (float*)d_out;

    const double c1d = solve_depressed_cubic((100.0 - 0.0) / 30.0);
    const double c2d = solve_depressed_cubic((100.0 - 300.0) / 30.0);

    const double DU = 1.0 / (double)(N_S - 1);
    const double TAU_MAX = 0.5 * 0.2 * 0.2 * 1.0;
    const double DT_NORM = TAU_MAX / (double)(N_T - 1);

    const float inv2du = (float)(1.0 / (2.0 * DU));
    const float invdu2 = (float)(1.0 / (DU * DU));
    const float inv2dt = (float)(1.0 / (2.0 * DT_NORM));

    const float pde_scale = (float)(1.0 / ((double)(N_S - 2) * (double)(N_T - 2)));
    const float bc_scale  = (float)(10.0 / (double)N_T);
    const float tc_scale  = (float)(10.0 / (double)N_S);

    bsloss_fused_kernel<<<NP_BLOCKS, BLOCK_THREADS>>>(V, out, (float)c1d, (float)c2d,
                                                      inv2du, invdu2, inv2dt,
                                                      pde_scale, bc_scale, tc_scale);
}